// round 7
// baseline (speedup 1.0000x reference)
#include <cuda_runtime.h>
#include <math.h>

#define Bb 8
#define Cc 128
#define Nn 65536
#define Ll 64
#define PTS 512            // points per kmain block
#define SLC 128            // kmain blocks per batch
#define CHUNKS 8           // 64-point chunks per block
#define TROW 65            // padded tile row stride

// Scratch in device globals. All fully overwritten every call.
__device__ float g_cpartC[Bb * SLC * Ll * Cc];   // 33.5 MB center partials
__device__ float g_vpart[Bb * SLC * Ll];
__device__ float g_cpart[Bb * SLC * Ll];
__device__ float g_cen[Bb * Ll * Cc];
__device__ float g_sqn[Bb * Cc];
__device__ float g_vc[Bb * Ll];

// ---------------------------------------------------------------------------
// kmain: fused single DRAM pass, software-pipelined.
// Per 64-pt chunk: STS staged regs -> tile[128][65]; barrier; issue LDGs for
// next chunk; compute (warps 0-3 scatter lane-owns-channel, warps 4-5 per-
// point stats); barrier. DRAM latency hides under compute.
// ---------------------------------------------------------------------------
__global__ __launch_bounds__(256, 3) void kmain(const float* __restrict__ pred,
                                                const int* __restrict__ label,
                                                float* __restrict__ out, int out_size) {
    extern __shared__ float sm[];
    float* tile = sm;                     // [128 * 65]
    float* acc  = sm + 128 * TROW;        // [64 lab][128 ch]
    float* vbin = acc + 8192;             // [64]
    float* cbin = vbin + 64;              // [64]
    int*   slab = (int*)(cbin + 64);      // [512]

    const int t = threadIdx.x;
    const int bid = blockIdx.x;
    const int b = bid >> 7, s = bid & (SLC - 1);
    const int n_base = s * PTS;
    const float* pb = pred + (size_t)b * Cc * Nn;

    if (bid == 0)                         // zero output before kfin's atomics
        for (int i = t; i < out_size; i += 256) out[i] = 0.0f;

    for (int i = t; i < Ll * Cc; i += 256) acc[i] = 0.0f;
    if (t < Ll) { vbin[t] = 0.0f; cbin[t] = 0.0f; }
    if (t < 128)                          // all 512 labels up front
        ((int4*)slab)[t] = ((const int4*)(label + b * Nn + n_base))[t];

    // preload chunk 0 into registers
    float4 V[8];
#pragma unroll
    for (int i = 0; i < 8; i++) {
        int idx = i * 256 + t;
        int c = idx >> 4, nq = (idx & 15) * 4;
        V[i] = *(const float4*)(pb + (size_t)c * Nn + n_base + nq);
    }
    __syncthreads();

#pragma unroll 1
    for (int ch = 0; ch < CHUNKS; ch++) {
        // ---- stage chunk ch into tile
#pragma unroll
        for (int i = 0; i < 8; i++) {
            int idx = i * 256 + t;
            int c = idx >> 4, nq = (idx & 15) * 4;
            float* r = tile + c * TROW + nq;
            r[0] = V[i].x; r[1] = V[i].y; r[2] = V[i].z; r[3] = V[i].w;
        }
        __syncthreads();

        // ---- issue loads for chunk ch+1 (latency overlaps compute below)
        {
            const int nc = (ch + 1) & 7;
#pragma unroll
            for (int i = 0; i < 8; i++) {
                int idx = i * 256 + t;
                int c = idx >> 4, nq = (idx & 15) * 4;
                V[i] = *(const float4*)(pb + (size_t)c * Nn + n_base + nc * 64 + nq);
            }
        }

        // ---- compute on tile
        const int* lp = slab + ch * 64;
        if (t < 128) {
            // scatter: thread owns channel t; acc[lab*128+t] bank=t%32 -> clean
            const float* tr = tile + t * TROW;
            float* ap = acc + t;
#pragma unroll 8
            for (int p = 0; p < 64; p++)
                ap[lp[p] * Cc] += tr[p];
        } else if (t < 192) {
            // per-point stats: thread owns point p, reads all 128 channels
            const int p = t - 128;
            float s1 = 0.f, s2 = 0.f;
#pragma unroll 16
            for (int j = 0; j < Cc; j++) {
                float x = tile[j * TROW + p];
                s1 += x;
                s2 = fmaf(x, x, s2);
            }
            float pn2 = fmaxf(s2 - s1 * s1 * (1.0f / Cc), 0.f);
            float d = sqrtf(pn2) - 0.5f;             // D_VAR
            float v = (d > 0.f) ? d * d : 0.f;
            int lb = lp[p];
            atomicAdd(&vbin[lb], v);
            atomicAdd(&cbin[lb], 1.f);
        }
        __syncthreads();
    }

    // ---- writeback per-slice partials (coalesced float4 stores)
    {
        float4* dst = (float4*)(g_cpartC + (size_t)bid * (Ll * Cc));
        const float4* src = (const float4*)acc;
#pragma unroll
        for (int k = 0; k < 8; k++) dst[k * 256 + t] = src[k * 256 + t];
    }
    if (t < Ll) {
        g_vpart[bid * Ll + t] = vbin[t];
        g_cpart[bid * Ll + t] = cbin[t];
    }
}

// ---------------------------------------------------------------------------
// kred: reduce slice partials -> normalized centers, sqn, var terms.
// Grid (16, B): block g covers channels [g*8, g*8+8), all 64 labels.
// 8 consecutive channels per cell-group = full 32B sectors.
// ---------------------------------------------------------------------------
__global__ __launch_bounds__(256) void kred() {
    const int g = blockIdx.x, b = blockIdx.y, t = threadIdx.x;
    __shared__ float ps[256];
    __shared__ float icnt[Ll];
    __shared__ float scen[Ll * 8];

    {   // counts (cooperative: 32 slices per thread)
        const int l = t & 63, sg = t >> 6;
        float cs = 0.f;
#pragma unroll 8
        for (int k = 0; k < 32; k++)
            cs += g_cpart[(b * SLC + sg * 32 + k) * Ll + l];
        ps[t] = cs;
    }
    __syncthreads();
    if (t < Ll) icnt[t] = 1.0f / (ps[t] + ps[t + 64] + ps[t + 128] + ps[t + 192]);
    __syncthreads();

    {   // center cells: 2 per thread, slices streamed
        int cell0 = t, cell1 = t + 256;
        int l0 = cell0 >> 3, c0 = g * 8 + (cell0 & 7);
        int l1 = cell1 >> 3, c1 = g * 8 + (cell1 & 7);
        float a0 = 0.f, a1 = 0.f;
#pragma unroll 8
        for (int sl = 0; sl < SLC; sl++) {
            size_t base = (size_t)(b * SLC + sl) * (Ll * Cc);
            a0 += g_cpartC[base + l0 * Cc + c0];
            a1 += g_cpartC[base + l1 * Cc + c1];
        }
        float cv0 = a0 * icnt[l0], cv1 = a1 * icnt[l1];
        g_cen[(size_t)b * Ll * Cc + l0 * Cc + c0] = cv0;
        g_cen[(size_t)b * Ll * Cc + l1 * Cc + c1] = cv1;
        scen[l0 * 8 + (cell0 & 7)] = cv0;
        scen[l1 * 8 + (cell1 & 7)] = cv1;
    }
    __syncthreads();

    if (g == 0) {   // vsum (reuses ps after barrier)
        const int l = t & 63, sg = t >> 6;
        float vv = 0.f;
#pragma unroll 8
        for (int k = 0; k < 32; k++)
            vv += g_vpart[(b * SLC + sg * 32 + k) * Ll + l];
        ps[t] = vv;
    }
    __syncthreads();

    if (t < 8) {
        float q = 0.f;
#pragma unroll 8
        for (int l = 0; l < Ll; l++) { float v = scen[l * 8 + t]; q = fmaf(v, v, q); }
        g_sqn[b * Cc + g * 8 + t] = q;
    }
    if (g == 0 && t < Ll)
        g_vc[b * Ll + t] = (ps[t] + ps[t + 64] + ps[t + 128] + ps[t + 192]) * icnt[t];
}

// ---------------------------------------------------------------------------
// kfin: pairwise hinge + reg + var assembly. Grid (16, B).
// ---------------------------------------------------------------------------
__global__ __launch_bounds__(256) void kfin(float* __restrict__ out) {
    const int q = blockIdx.x, b = blockIdx.y, t = threadIdx.x;
    __shared__ float cen[Ll][Cc];    // 32 KB
    __shared__ float sq[Cc];
    __shared__ float red[8];

    {   // vectorized centers load
        const float4* src = (const float4*)(g_cen + (size_t)b * Ll * Cc);
        float4* dst = (float4*)&cen[0][0];
#pragma unroll
        for (int i = 0; i < 8; i++) dst[i * 256 + t] = src[i * 256 + t];
    }
    if (t < Cc) sq[t] = g_sqn[b * Cc + t];
    __syncthreads();

    const int cc = t & 127;
    const int d0 = q * 8 + (t >> 7) * 4;
    float g0 = 0.f, g1 = 0.f, g2 = 0.f, g3 = 0.f;
#pragma unroll 8
    for (int l = 0; l < Ll; l++) {
        float a = cen[l][cc];
        g0 = fmaf(a, cen[l][d0 + 0], g0);
        g1 = fmaf(a, cen[l][d0 + 1], g1);
        g2 = fmaf(a, cen[l][d0 + 2], g2);
        g3 = fmaf(a, cen[l][d0 + 3], g3);
    }
    float gg[4] = {g0, g1, g2, g3};
    float local = 0.f;
#pragma unroll
    for (int j = 0; j < 4; j++) {
        float sqd = fmaxf(sq[cc] + sq[d0 + j] - 2.0f * gg[j], 0.f);
        float dist = (sqd > 0.f) ? sqrtf(sqd) : 0.f;
        float h = fmaxf(3.0f - dist, 0.f);        // 2*D_DIST
        local = fmaf(h, h, local);
    }
    local *= (1.0f / 8064.0f);                    // P_DIST / (2*L*(L-1))

    if (q == 0 && t < Cc) {
        local += 0.001f * sqrtf(sq[t]) * (1.0f / 64.0f);        // l_reg
        if (t < Ll) local += g_vc[b * Ll + t] * (1.0f / 64.0f); // var
    }

    for (int off = 16; off > 0; off >>= 1)
        local += __shfl_down_sync(0xFFFFFFFFu, local, off);
    if ((t & 31) == 0) red[t >> 5] = local;
    __syncthreads();
    if (t == 0) {
        float s = 0.f;
#pragma unroll
        for (int w = 0; w < 8; w++) s += red[w];
        atomicAdd(out, s);
    }
}

// ---------------------------------------------------------------------------
extern "C" void kernel_launch(void* const* d_in, const int* in_sizes, int n_in,
                              void* d_out, int out_size) {
    const float* pred  = (const float*)d_in[0];
    const int*   label = (const int*)d_in[1];
    float* out = (float*)d_out;

    const int smem_bytes = (128 * TROW + 8192 + 64 + 64 + 512) * 4;   // 68608
    cudaFuncSetAttribute(kmain, cudaFuncAttributeMaxDynamicSharedMemorySize, smem_bytes);

    kmain<<<Bb * SLC, 256, smem_bytes>>>(pred, label, out, out_size);
    kred<<<dim3(16, Bb), 256>>>();
    kfin<<<dim3(16, Bb), 256>>>(out);
}

// round 8
// speedup vs baseline: 1.4529x; 1.4529x over previous
#include <cuda_runtime.h>
#include <math.h>

#define Bb 8
#define Cc 128
#define Nn 65536
#define Ll 64
#define PSLABS 64                 // point slabs per batch (1024 pts each)
#define NPT (Bb * PSLABS)         // 512 point blocks
#define NCH (Bb * Cc)             // 1024 channel blocks

// Scratch in device globals. All fully overwritten every call.
__device__ unsigned int g_lab8[Bb * Nn / 4];     // packed uint8 labels
__device__ float g_censum[Bb * Ll * Cc];
__device__ float g_vpart[NPT * Ll];
__device__ float g_cpart[NPT * Ll];
__device__ float g_cen[Bb * Ll * Cc];
__device__ float g_sqn[Bb * Cc];
__device__ float g_vc[Bb * Ll];

// ---------------------------------------------------------------------------
// klab: pack int32 labels (values < 64) into uint8x4 words. 512 blocks.
// ---------------------------------------------------------------------------
__global__ __launch_bounds__(256) void klab(const int* __restrict__ label) {
    int i = blockIdx.x * 256 + threadIdx.x;          // 131072 words
    int4 l = ((const int4*)label)[i];
    g_lab8[i] = (unsigned)l.x | ((unsigned)l.y << 8) |
                ((unsigned)l.z << 16) | ((unsigned)l.w << 24);
}

// ---------------------------------------------------------------------------
// kboth: merged grid, types interleaved 1 point : 2 channel (bid%3).
//   point block : (b, slab of 1024 pts) -> var/count partials
//   channel block: (b, c) -> unnormalized center sums (2-copy chain RMW)
// ---------------------------------------------------------------------------
__global__ __launch_bounds__(256, 3) void kboth(const float* __restrict__ pred,
                                                float* __restrict__ out, int out_size) {
    extern __shared__ float sm[];
    const int t = threadIdx.x;
    const int bid = blockIdx.x;
    const int g = bid / 3, r = bid - 3 * g;

    if (bid == 0)                        // zero output before kfin's atomics
        for (int i = t; i < out_size; i += 256) out[i] = 0.0f;

    if (r == 0) {
        // ================= point pass =================
        const int b = g >> 6, slab = g & 63;
        const int n0 = slab * 1024;                     // 256 thr x 4 pts
        const float4* p4 = (const float4*)(pred + (size_t)b * Cc * Nn + n0);

        float s1x = 0.f, s1y = 0.f, s1z = 0.f, s1w = 0.f;
        float s2x = 0.f, s2y = 0.f, s2z = 0.f, s2w = 0.f;
        float4 VA[8], VB[8];
#pragma unroll
        for (int k = 0; k < 8; k++) VA[k] = p4[(size_t)k * (Nn / 4) + t];

#pragma unroll 1
        for (int cg = 0; cg < 16; cg += 2) {
#pragma unroll
            for (int k = 0; k < 8; k++)
                VB[k] = p4[(size_t)((cg + 1) * 8 + k) * (Nn / 4) + t];
#pragma unroll
            for (int k = 0; k < 8; k++) {
                s1x += VA[k].x; s2x = fmaf(VA[k].x, VA[k].x, s2x);
                s1y += VA[k].y; s2y = fmaf(VA[k].y, VA[k].y, s2y);
                s1z += VA[k].z; s2z = fmaf(VA[k].z, VA[k].z, s2z);
                s1w += VA[k].w; s2w = fmaf(VA[k].w, VA[k].w, s2w);
            }
            if (cg + 2 < 16) {
#pragma unroll
                for (int k = 0; k < 8; k++)
                    VA[k] = p4[(size_t)((cg + 2) * 8 + k) * (Nn / 4) + t];
            }
#pragma unroll
            for (int k = 0; k < 8; k++) {
                s1x += VB[k].x; s2x = fmaf(VB[k].x, VB[k].x, s2x);
                s1y += VB[k].y; s2y = fmaf(VB[k].y, VB[k].y, s2y);
                s1z += VB[k].z; s2z = fmaf(VB[k].z, VB[k].z, s2z);
                s1w += VB[k].w; s2w = fmaf(VB[k].w, VB[k].w, s2w);
            }
        }
        unsigned lu = g_lab8[b * (Nn / 4) + (n0 / 4) + t];

        float* vbin = sm;            // [64]
        float* cbin = sm + 64;       // [64]
        if (t < Ll) { vbin[t] = 0.f; cbin[t] = 0.f; }
        __syncthreads();
        {
            float pn2, d, v;
            pn2 = fmaxf(s2x - s1x * s1x * (1.0f / Cc), 0.f);
            d = sqrtf(pn2) - 0.5f; v = (d > 0.f) ? d * d : 0.f;
            atomicAdd(&vbin[lu & 255], v); atomicAdd(&cbin[lu & 255], 1.f);
            pn2 = fmaxf(s2y - s1y * s1y * (1.0f / Cc), 0.f);
            d = sqrtf(pn2) - 0.5f; v = (d > 0.f) ? d * d : 0.f;
            atomicAdd(&vbin[(lu >> 8) & 255], v); atomicAdd(&cbin[(lu >> 8) & 255], 1.f);
            pn2 = fmaxf(s2z - s1z * s1z * (1.0f / Cc), 0.f);
            d = sqrtf(pn2) - 0.5f; v = (d > 0.f) ? d * d : 0.f;
            atomicAdd(&vbin[(lu >> 16) & 255], v); atomicAdd(&cbin[(lu >> 16) & 255], 1.f);
            pn2 = fmaxf(s2w - s1w * s1w * (1.0f / Cc), 0.f);
            d = sqrtf(pn2) - 0.5f; v = (d > 0.f) ? d * d : 0.f;
            atomicAdd(&vbin[lu >> 24], v); atomicAdd(&cbin[lu >> 24], 1.f);
        }
        __syncthreads();
        if (t < Ll) {
            g_vpart[g * Ll + t] = vbin[t];
            g_cpart[g * Ll + t] = cbin[t];
        }
    } else {
        // ================= channel pass =================
        const int id = 2 * g + (r - 1);                 // 0..1023
        const int c = id & 127, b = id >> 7;
        float* acc = sm;             // [2 copies][64 labels][128 cols]
        float* red = sm + 16384;     // [256]

        for (int i = t; i < 16384; i += 256) acc[i] = 0.f;
        __syncthreads();

        const float4* p4 = (const float4*)(pred + (size_t)b * Cc * Nn + (size_t)c * Nn);
        const unsigned* lp = g_lab8 + b * (Nn / 4);
        float* ap = acc + (t >> 7) * 8192 + (t & 127);  // private column

        float4 XA[4], XB[4]; unsigned LA[4], LB[4];
#pragma unroll
        for (int k = 0; k < 4; k++) { XA[k] = p4[k * 256 + t]; LA[k] = lp[k * 256 + t]; }

#pragma unroll 1
        for (int s = 0; s < 16; s += 2) {
#pragma unroll
            for (int k = 0; k < 4; k++) {
                int idx = ((s + 1) * 4 + k) * 256 + t;
                XB[k] = p4[idx]; LB[k] = lp[idx];
            }
#pragma unroll
            for (int k = 0; k < 4; k++) {
                ap[(LA[k] & 255) * 128]         += XA[k].x;   // bank=col%32: clean
                ap[((LA[k] >> 8) & 255) * 128]  += XA[k].y;
                ap[((LA[k] >> 16) & 255) * 128] += XA[k].z;
                ap[(LA[k] >> 24) * 128]         += XA[k].w;
            }
            if (s + 2 < 16) {
#pragma unroll
                for (int k = 0; k < 4; k++) {
                    int idx = ((s + 2) * 4 + k) * 256 + t;
                    XA[k] = p4[idx]; LA[k] = lp[idx];
                }
            }
#pragma unroll
            for (int k = 0; k < 4; k++) {
                ap[(LB[k] & 255) * 128]         += XB[k].x;
                ap[((LB[k] >> 8) & 255) * 128]  += XB[k].y;
                ap[((LB[k] >> 16) & 255) * 128] += XB[k].z;
                ap[(LB[k] >> 24) * 128]         += XB[k].w;
            }
        }
        __syncthreads();

        // diagonal reduce (conflict-free despite stride 128)
        const int l = t & 63, q = t >> 6;
        float s = 0.f;
#pragma unroll 8
        for (int jj = 0; jj < 32; jj++) {
            int j = (q * 32 + jj + t) & 127;
            s += acc[l * 128 + j] + acc[8192 + l * 128 + j];
        }
        red[t] = s;
        __syncthreads();
        if (t < Ll)
            g_censum[((size_t)b * Ll + t) * Cc + c] =
                red[t] + red[t + 64] + red[t + 128] + red[t + 192];
    }
}

// ---------------------------------------------------------------------------
// kred: per-batch counts, normalized centers, sqn, var. Grid = Bb.
// Reads only small L2-resident partials (384 KB total).
// ---------------------------------------------------------------------------
__global__ __launch_bounds__(256) void kred() {
    const int b = blockIdx.x, t = threadIdx.x;
    __shared__ float ps[256];
    __shared__ float qs[256];
    __shared__ float icnt[Ll];
    __shared__ float scen[Ll][Cc];

    {   // counts + vsums: 16 slabs per thread
        const int l = t & 63, sg = t >> 6;
        float cs = 0.f, vv = 0.f;
#pragma unroll 4
        for (int k = 0; k < 16; k++) {
            int idx = (b * PSLABS + sg * 16 + k) * Ll + l;
            cs += g_cpart[idx];
            vv += g_vpart[idx];
        }
        ps[t] = cs; qs[t] = vv;
    }
    __syncthreads();
    if (t < Ll) {
        float ctot = ps[t] + ps[t + 64] + ps[t + 128] + ps[t + 192];
        icnt[t] = 1.0f / ctot;
        g_vc[b * Ll + t] = (qs[t] + qs[t + 64] + qs[t + 128] + qs[t + 192]) / ctot;
    }
    __syncthreads();

    for (int i = t; i < Ll * Cc; i += 256) {
        int l = i >> 7;
        float cv = g_censum[(size_t)b * Ll * Cc + i] * icnt[l];
        scen[l][i & 127] = cv;
        g_cen[(size_t)b * Ll * Cc + i] = cv;
    }
    __syncthreads();

    {   // sqn: half-column per thread then combine
        const int c = t & 127, h = t >> 7;
        float s = 0.f;
#pragma unroll 8
        for (int l = h * 32; l < h * 32 + 32; l++) { float v = scen[l][c]; s = fmaf(v, v, s); }
        ps[t] = s;
    }
    __syncthreads();
    if (t < Cc) g_sqn[b * Cc + t] = ps[t] + ps[t + 128];
}

// ---------------------------------------------------------------------------
// kfin: pairwise hinge + reg + var assembly. Grid (16, Bb).
// ---------------------------------------------------------------------------
__global__ __launch_bounds__(256) void kfin(float* __restrict__ out) {
    const int q = blockIdx.x, b = blockIdx.y, t = threadIdx.x;
    __shared__ float cen[Ll][Cc];    // 32 KB
    __shared__ float sq[Cc];
    __shared__ float red[8];

    {   // vectorized centers load
        const float4* src = (const float4*)(g_cen + (size_t)b * Ll * Cc);
        float4* dst = (float4*)&cen[0][0];
#pragma unroll
        for (int i = 0; i < 8; i++) dst[i * 256 + t] = src[i * 256 + t];
    }
    if (t < Cc) sq[t] = g_sqn[b * Cc + t];
    __syncthreads();

    const int cc = t & 127;
    const int d0 = q * 8 + (t >> 7) * 4;
    float g0 = 0.f, g1 = 0.f, g2 = 0.f, g3 = 0.f;
#pragma unroll 8
    for (int l = 0; l < Ll; l++) {
        float a = cen[l][cc];
        g0 = fmaf(a, cen[l][d0 + 0], g0);
        g1 = fmaf(a, cen[l][d0 + 1], g1);
        g2 = fmaf(a, cen[l][d0 + 2], g2);
        g3 = fmaf(a, cen[l][d0 + 3], g3);
    }
    float gg[4] = {g0, g1, g2, g3};
    float local = 0.f;
#pragma unroll
    for (int j = 0; j < 4; j++) {
        float sqd = fmaxf(sq[cc] + sq[d0 + j] - 2.0f * gg[j], 0.f);
        float dist = (sqd > 0.f) ? sqrtf(sqd) : 0.f;
        float h = fmaxf(3.0f - dist, 0.f);        // 2*D_DIST
        local = fmaf(h, h, local);
    }
    local *= (1.0f / 8064.0f);                    // P_DIST / (2*L*(L-1))

    if (q == 0 && t < Cc) {
        local += 0.001f * sqrtf(sq[t]) * (1.0f / 64.0f);        // l_reg
        if (t < Ll) local += g_vc[b * Ll + t] * (1.0f / 64.0f); // var
    }

    for (int off = 16; off > 0; off >>= 1)
        local += __shfl_down_sync(0xFFFFFFFFu, local, off);
    if ((t & 31) == 0) red[t >> 5] = local;
    __syncthreads();
    if (t == 0) {
        float s = 0.f;
#pragma unroll
        for (int w = 0; w < 8; w++) s += red[w];
        atomicAdd(out, s);
    }
}

// ---------------------------------------------------------------------------
extern "C" void kernel_launch(void* const* d_in, const int* in_sizes, int n_in,
                              void* d_out, int out_size) {
    const float* pred  = (const float*)d_in[0];
    const int*   label = (const int*)d_in[1];
    float* out = (float*)d_out;

    const int smem_bytes = (16384 + 256) * 4;     // 66560
    cudaFuncSetAttribute(kboth, cudaFuncAttributeMaxDynamicSharedMemorySize, smem_bytes);

    klab<<<Bb * Nn / 4 / 256, 256>>>(label);
    kboth<<<NPT + NCH, 256, smem_bytes>>>(pred, out, out_size);
    kred<<<Bb, 256>>>();
    kfin<<<dim3(16, Bb), 256>>>(out);
}

// round 10
// speedup vs baseline: 1.6258x; 1.1190x over previous
#include <cuda_runtime.h>
#include <math.h>

#define Bb 8
#define Cc 128
#define Nn 65536
#define Ll 64
#define PSLABS 64                 // point slabs per batch (1024 pts each)
#define NPT (Bb * PSLABS)         // 512 point blocks
#define NCH (Bb * Cc)             // 1024 channel blocks

// Scratch in device globals. All fully overwritten every call.
__device__ unsigned int g_lab8[Bb * Nn / 4];     // packed uint8 labels
__device__ float g_censum[Bb * Ll * Cc];
__device__ float g_vpart[NPT * Ll];
__device__ float g_cpart[NPT * Ll];

// float4 load with L2 evict-last via cache-policy hint: pred lines are
// touched exactly twice (point pass + channel pass); retaining them turns
// the 2nd touch into an L2 hit (per-wave working set ~74MB < 126MB L2).
__device__ __forceinline__ float4 ldg_el(const float4* p) {
    float4 v;
    unsigned long long pol;
    asm volatile("createpolicy.fractional.L2::evict_last.b64 %0, 1.0;" : "=l"(pol));
    asm volatile("ld.global.nc.L2::cache_hint.v4.f32 {%0,%1,%2,%3}, [%4], %5;"
                 : "=f"(v.x), "=f"(v.y), "=f"(v.z), "=f"(v.w)
                 : "l"(p), "l"(pol));
    return v;
}

// ---------------------------------------------------------------------------
// klab: pack int32 labels (values < 64) into uint8x4 words.
// ---------------------------------------------------------------------------
__global__ __launch_bounds__(256) void klab(const int* __restrict__ label) {
    int i = blockIdx.x * 256 + threadIdx.x;          // 131072 words
    int4 l = ((const int4*)label)[i];
    g_lab8[i] = (unsigned)l.x | ((unsigned)l.y << 8) |
                ((unsigned)l.z << 16) | ((unsigned)l.w << 24);
}

// ---------------------------------------------------------------------------
// kboth: merged grid, types interleaved 1 point : 2 channel (bid%3) so the
// concurrent window stays batch-aligned (enables cross-pass L2 reuse).
// ---------------------------------------------------------------------------
__global__ __launch_bounds__(256, 3) void kboth(const float* __restrict__ pred,
                                                float* __restrict__ out, int out_size) {
    extern __shared__ float sm[];
    const int t = threadIdx.x;
    const int bid = blockIdx.x;
    const int g = bid / 3, r = bid - 3 * g;

    if (bid == 0)                        // zero output before kfin's atomics
        for (int i = t; i < out_size; i += 256) out[i] = 0.0f;

    if (r == 0) {
        // ================= point pass =================
        const int b = g >> 6, slab = g & 63;
        const int n0 = slab * 1024;                     // 256 thr x 4 pts
        const float4* p4 = (const float4*)(pred + (size_t)b * Cc * Nn + n0);

        float s1x = 0.f, s1y = 0.f, s1z = 0.f, s1w = 0.f;
        float s2x = 0.f, s2y = 0.f, s2z = 0.f, s2w = 0.f;
        float4 VA[8], VB[8];
#pragma unroll
        for (int k = 0; k < 8; k++) VA[k] = ldg_el(p4 + (size_t)k * (Nn / 4) + t);

#pragma unroll 1
        for (int cg = 0; cg < 16; cg += 2) {
#pragma unroll
            for (int k = 0; k < 8; k++)
                VB[k] = ldg_el(p4 + (size_t)((cg + 1) * 8 + k) * (Nn / 4) + t);
#pragma unroll
            for (int k = 0; k < 8; k++) {
                s1x += VA[k].x; s2x = fmaf(VA[k].x, VA[k].x, s2x);
                s1y += VA[k].y; s2y = fmaf(VA[k].y, VA[k].y, s2y);
                s1z += VA[k].z; s2z = fmaf(VA[k].z, VA[k].z, s2z);
                s1w += VA[k].w; s2w = fmaf(VA[k].w, VA[k].w, s2w);
            }
            if (cg + 2 < 16) {
#pragma unroll
                for (int k = 0; k < 8; k++)
                    VA[k] = ldg_el(p4 + (size_t)((cg + 2) * 8 + k) * (Nn / 4) + t);
            }
#pragma unroll
            for (int k = 0; k < 8; k++) {
                s1x += VB[k].x; s2x = fmaf(VB[k].x, VB[k].x, s2x);
                s1y += VB[k].y; s2y = fmaf(VB[k].y, VB[k].y, s2y);
                s1z += VB[k].z; s2z = fmaf(VB[k].z, VB[k].z, s2z);
                s1w += VB[k].w; s2w = fmaf(VB[k].w, VB[k].w, s2w);
            }
        }
        unsigned lu = g_lab8[b * (Nn / 4) + (n0 / 4) + t];

        float* vbin = sm;            // [64]
        float* cbin = sm + 64;       // [64]
        if (t < Ll) { vbin[t] = 0.f; cbin[t] = 0.f; }
        __syncthreads();
        {
            float pn2, d, v;
            pn2 = fmaxf(s2x - s1x * s1x * (1.0f / Cc), 0.f);
            d = sqrtf(pn2) - 0.5f; v = (d > 0.f) ? d * d : 0.f;
            atomicAdd(&vbin[lu & 255], v); atomicAdd(&cbin[lu & 255], 1.f);
            pn2 = fmaxf(s2y - s1y * s1y * (1.0f / Cc), 0.f);
            d = sqrtf(pn2) - 0.5f; v = (d > 0.f) ? d * d : 0.f;
            atomicAdd(&vbin[(lu >> 8) & 255], v); atomicAdd(&cbin[(lu >> 8) & 255], 1.f);
            pn2 = fmaxf(s2z - s1z * s1z * (1.0f / Cc), 0.f);
            d = sqrtf(pn2) - 0.5f; v = (d > 0.f) ? d * d : 0.f;
            atomicAdd(&vbin[(lu >> 16) & 255], v); atomicAdd(&cbin[(lu >> 16) & 255], 1.f);
            pn2 = fmaxf(s2w - s1w * s1w * (1.0f / Cc), 0.f);
            d = sqrtf(pn2) - 0.5f; v = (d > 0.f) ? d * d : 0.f;
            atomicAdd(&vbin[lu >> 24], v); atomicAdd(&cbin[lu >> 24], 1.f);
        }
        __syncthreads();
        if (t < Ll) {
            g_vpart[g * Ll + t] = vbin[t];
            g_cpart[g * Ll + t] = cbin[t];
        }
    } else {
        // ================= channel pass =================
        const int id = 2 * g + (r - 1);                 // 0..1023
        const int c = id & 127, b = id >> 7;
        float* acc = sm;             // [2 copies][64 labels][128 cols]
        float* red = sm + 16384;     // [256]

        for (int i = t; i < 16384; i += 256) acc[i] = 0.f;
        __syncthreads();

        const float4* p4 = (const float4*)(pred + (size_t)b * Cc * Nn + (size_t)c * Nn);
        const unsigned* lp = g_lab8 + b * (Nn / 4);
        float* ap = acc + (t >> 7) * 8192 + (t & 127);  // private column

        float4 XA[4], XB[4]; unsigned LA[4], LB[4];
#pragma unroll
        for (int k = 0; k < 4; k++) { XA[k] = ldg_el(p4 + k * 256 + t); LA[k] = lp[k * 256 + t]; }

#pragma unroll 1
        for (int s = 0; s < 16; s += 2) {
#pragma unroll
            for (int k = 0; k < 4; k++) {
                int idx = ((s + 1) * 4 + k) * 256 + t;
                XB[k] = ldg_el(p4 + idx); LB[k] = lp[idx];
            }
#pragma unroll
            for (int k = 0; k < 4; k++) {
                ap[(LA[k] & 255) * 128]         += XA[k].x;   // bank=col%32: clean
                ap[((LA[k] >> 8) & 255) * 128]  += XA[k].y;
                ap[((LA[k] >> 16) & 255) * 128] += XA[k].z;
                ap[(LA[k] >> 24) * 128]         += XA[k].w;
            }
            if (s + 2 < 16) {
#pragma unroll
                for (int k = 0; k < 4; k++) {
                    int idx = ((s + 2) * 4 + k) * 256 + t;
                    XA[k] = ldg_el(p4 + idx); LA[k] = lp[idx];
                }
            }
#pragma unroll
            for (int k = 0; k < 4; k++) {
                ap[(LB[k] & 255) * 128]         += XB[k].x;
                ap[((LB[k] >> 8) & 255) * 128]  += XB[k].y;
                ap[((LB[k] >> 16) & 255) * 128] += XB[k].z;
                ap[(LB[k] >> 24) * 128]         += XB[k].w;
            }
        }
        __syncthreads();

        // diagonal reduce (conflict-free despite stride 128)
        const int l = t & 63, q = t >> 6;
        float s = 0.f;
#pragma unroll 8
        for (int jj = 0; jj < 32; jj++) {
            int j = (q * 32 + jj + t) & 127;
            s += acc[l * 128 + j] + acc[8192 + l * 128 + j];
        }
        red[t] = s;
        __syncthreads();
        if (t < Ll)
            g_censum[((size_t)b * Ll + t) * Cc + c] =
                red[t] + red[t + 64] + red[t + 128] + red[t + 192];
    }
}

// ---------------------------------------------------------------------------
// kfin: merged finalize. Grid (32, Bb) = 256 blocks; block q covers
// d in [q*4, q*4+4). Each block re-derives counts/centers from the small
// L2-resident partials; q==0 adds reg + var terms.
// ---------------------------------------------------------------------------
__global__ __launch_bounds__(256) void kfin(float* __restrict__ out) {
    const int q = blockIdx.x, b = blockIdx.y, t = threadIdx.x;
    __shared__ float cen[Ll][Cc];    // 32 KB
    __shared__ float ps[256];
    __shared__ float qs[256];
    __shared__ float icnt[Ll];
    __shared__ float vc[Ll];
    __shared__ float sq[Cc];
    __shared__ float red[8];

    {   // counts + vsums: 16 slabs per thread (L2-resident, 16KB/batch)
        const int l = t & 63, sg = t >> 6;
        float cs = 0.f, vv = 0.f;
#pragma unroll 4
        for (int k = 0; k < 16; k++) {
            int idx = (b * PSLABS + sg * 16 + k) * Ll + l;
            cs += g_cpart[idx];
            vv += g_vpart[idx];
        }
        ps[t] = cs; qs[t] = vv;
    }
    __syncthreads();
    if (t < Ll) {
        float ctot = ps[t] + ps[t + 64] + ps[t + 128] + ps[t + 192];
        icnt[t] = 1.0f / ctot;
        vc[t] = (qs[t] + qs[t + 64] + qs[t + 128] + qs[t + 192]) / ctot;
    }
    __syncthreads();

    {   // normalized centers (float4: 4 consecutive c share one l)
        const float4* src = (const float4*)(g_censum + (size_t)b * Ll * Cc);
        float4* dst = (float4*)&cen[0][0];
#pragma unroll
        for (int i = 0; i < 8; i++) {
            int idx = i * 256 + t;                 // 2048 float4 cells
            float ic = icnt[idx >> 5];
            float4 v = src[idx];
            v.x *= ic; v.y *= ic; v.z *= ic; v.w *= ic;
            dst[idx] = v;
        }
    }
    __syncthreads();

    {   // sqn: half-column per thread then combine
        const int c = t & 127, h = t >> 7;
        float s = 0.f;
#pragma unroll 8
        for (int l = h * 32; l < h * 32 + 32; l++) { float v = cen[l][c]; s = fmaf(v, v, s); }
        ps[t] = s;
    }
    __syncthreads();
    if (t < Cc) sq[t] = ps[t] + ps[t + 128];
    __syncthreads();

    // gram slice: 2 accumulators per thread
    const int cc = t & 127;
    const int d0 = q * 4 + (t >> 7) * 2;
    float g0 = 0.f, g1 = 0.f;
#pragma unroll 8
    for (int l = 0; l < Ll; l++) {
        float a = cen[l][cc];
        g0 = fmaf(a, cen[l][d0 + 0], g0);
        g1 = fmaf(a, cen[l][d0 + 1], g1);
    }
    float local = 0.f;
#pragma unroll
    for (int j = 0; j < 2; j++) {
        float gg = j ? g1 : g0;
        float sqd = fmaxf(sq[cc] + sq[d0 + j] - 2.0f * gg, 0.f);
        float dist = (sqd > 0.f) ? sqrtf(sqd) : 0.f;
        float h = fmaxf(3.0f - dist, 0.f);        // 2*D_DIST
        local = fmaf(h, h, local);
    }
    local *= (1.0f / 8064.0f);                    // P_DIST / (2*L*(L-1))

    if (q == 0 && t < Cc) {
        local += 0.001f * sqrtf(sq[t]) * (1.0f / 64.0f);   // l_reg
        if (t < Ll) local += vc[t] * (1.0f / 64.0f);       // var
    }

    for (int off = 16; off > 0; off >>= 1)
        local += __shfl_down_sync(0xFFFFFFFFu, local, off);
    if ((t & 31) == 0) red[t >> 5] = local;
    __syncthreads();
    if (t == 0) {
        float s = 0.f;
#pragma unroll
        for (int w = 0; w < 8; w++) s += red[w];
        atomicAdd(out, s);
    }
}

// ---------------------------------------------------------------------------
extern "C" void kernel_launch(void* const* d_in, const int* in_sizes, int n_in,
                              void* d_out, int out_size) {
    const float* pred  = (const float*)d_in[0];
    const int*   label = (const int*)d_in[1];
    float* out = (float*)d_out;

    const int smem_bytes = (16384 + 256) * 4;     // 66560
    cudaFuncSetAttribute(kboth, cudaFuncAttributeMaxDynamicSharedMemorySize, smem_bytes);

    klab<<<Bb * Nn / 4 / 256, 256>>>(label);
    kboth<<<NPT + NCH, 256, smem_bytes>>>(pred, out, out_size);
    kfin<<<dim3(32, Bb), 256>>>(out);
}

// round 11
// speedup vs baseline: 1.6514x; 1.0158x over previous
#include <cuda_runtime.h>
#include <math.h>

#define Bb 8
#define Cc 128
#define Nn 65536
#define Ll 64
#define PSLABS 64                 // point slabs per batch (1024 pts each)
#define NPT (Bb * PSLABS)         // 512 point blocks
#define NCHH (Bb * Cc * 2)        // 2048 channel half-blocks
#define NBLK (NPT + NCHH)         // 2560

// Scratch in device globals. g_censum zeroed by klab then atomically
// accumulated (exactly 2 adds per cell -> commutative -> deterministic).
__device__ unsigned int g_lab8[Bb * Nn / 4];     // packed uint8 labels
__device__ float g_censum[Bb * Ll * Cc];
__device__ float g_vpart[NPT * Ll];
__device__ float g_cpart[NPT * Ll];

// float4 load with L2 evict-last via cache-policy hint: pred lines are
// touched exactly twice (point pass + channel pass); retaining them turns
// the 2nd touch into an L2 hit (per-wave working set ~74MB < 126MB L2).
__device__ __forceinline__ float4 ldg_el(const float4* p) {
    float4 v;
    unsigned long long pol;
    asm volatile("createpolicy.fractional.L2::evict_last.b64 %0, 1.0;" : "=l"(pol));
    asm volatile("ld.global.nc.L2::cache_hint.v4.f32 {%0,%1,%2,%3}, [%4], %5;"
                 : "=f"(v.x), "=f"(v.y), "=f"(v.z), "=f"(v.w)
                 : "l"(p), "l"(pol));
    return v;
}

// ---------------------------------------------------------------------------
// klab: pack int32 labels into uint8x4 (4 int4 per thread, MLP=4) and zero
// the atomically-accumulated censum buffer.
// ---------------------------------------------------------------------------
__global__ __launch_bounds__(256) void klab(const int* __restrict__ label) {
    const int t = blockIdx.x * 256 + threadIdx.x;      // 32768 threads
    const int4* l4 = (const int4*)label;
#pragma unroll
    for (int k = 0; k < 4; k++) {
        int i = t * 4 + k;
        int4 l = l4[i];
        g_lab8[i] = (unsigned)l.x | ((unsigned)l.y << 8) |
                    ((unsigned)l.z << 16) | ((unsigned)l.w << 24);
    }
#pragma unroll
    for (int k = 0; k < 2; k++)
        g_censum[k * 32768 + t] = 0.0f;
}

// ---------------------------------------------------------------------------
// kboth: merged grid, 1 point : 4 channel-half interleave (bid%5), batch-
// aligned so both passes touch the same batch within one L2 residency window.
// ---------------------------------------------------------------------------
__global__ __launch_bounds__(256, 3) void kboth(const float* __restrict__ pred,
                                                float* __restrict__ out, int out_size) {
    extern __shared__ float sm[];
    const int t = threadIdx.x;
    const int bid = blockIdx.x;
    const int g5 = bid / 5, r5 = bid - 5 * g5;

    if (bid == 0)                        // zero output before kfin's atomics
        for (int i = t; i < out_size; i += 256) out[i] = 0.0f;

    if (r5 == 0) {
        // ================= point pass (1024 pts) =================
        const int b = g5 >> 6, slab = g5 & 63;
        const int n0 = slab * 1024;                     // 256 thr x 4 pts
        const float4* p4 = (const float4*)(pred + (size_t)b * Cc * Nn + n0);

        float s1x = 0.f, s1y = 0.f, s1z = 0.f, s1w = 0.f;
        float s2x = 0.f, s2y = 0.f, s2z = 0.f, s2w = 0.f;
        float4 VA[8], VB[8];
#pragma unroll
        for (int k = 0; k < 8; k++) VA[k] = ldg_el(p4 + (size_t)k * (Nn / 4) + t);

#pragma unroll 1
        for (int cg = 0; cg < 16; cg += 2) {
#pragma unroll
            for (int k = 0; k < 8; k++)
                VB[k] = ldg_el(p4 + (size_t)((cg + 1) * 8 + k) * (Nn / 4) + t);
#pragma unroll
            for (int k = 0; k < 8; k++) {
                s1x += VA[k].x; s2x = fmaf(VA[k].x, VA[k].x, s2x);
                s1y += VA[k].y; s2y = fmaf(VA[k].y, VA[k].y, s2y);
                s1z += VA[k].z; s2z = fmaf(VA[k].z, VA[k].z, s2z);
                s1w += VA[k].w; s2w = fmaf(VA[k].w, VA[k].w, s2w);
            }
            if (cg + 2 < 16) {
#pragma unroll
                for (int k = 0; k < 8; k++)
                    VA[k] = ldg_el(p4 + (size_t)((cg + 2) * 8 + k) * (Nn / 4) + t);
            }
#pragma unroll
            for (int k = 0; k < 8; k++) {
                s1x += VB[k].x; s2x = fmaf(VB[k].x, VB[k].x, s2x);
                s1y += VB[k].y; s2y = fmaf(VB[k].y, VB[k].y, s2y);
                s1z += VB[k].z; s2z = fmaf(VB[k].z, VB[k].z, s2z);
                s1w += VB[k].w; s2w = fmaf(VB[k].w, VB[k].w, s2w);
            }
        }
        unsigned lu = g_lab8[b * (Nn / 4) + (n0 / 4) + t];

        float* vbin = sm;            // [64]
        float* cbin = sm + 64;       // [64]
        if (t < Ll) { vbin[t] = 0.f; cbin[t] = 0.f; }
        __syncthreads();
        {
            float pn2, d, v;
            pn2 = fmaxf(s2x - s1x * s1x * (1.0f / Cc), 0.f);
            d = sqrtf(pn2) - 0.5f; v = (d > 0.f) ? d * d : 0.f;
            atomicAdd(&vbin[lu & 255], v); atomicAdd(&cbin[lu & 255], 1.f);
            pn2 = fmaxf(s2y - s1y * s1y * (1.0f / Cc), 0.f);
            d = sqrtf(pn2) - 0.5f; v = (d > 0.f) ? d * d : 0.f;
            atomicAdd(&vbin[(lu >> 8) & 255], v); atomicAdd(&cbin[(lu >> 8) & 255], 1.f);
            pn2 = fmaxf(s2z - s1z * s1z * (1.0f / Cc), 0.f);
            d = sqrtf(pn2) - 0.5f; v = (d > 0.f) ? d * d : 0.f;
            atomicAdd(&vbin[(lu >> 16) & 255], v); atomicAdd(&cbin[(lu >> 16) & 255], 1.f);
            pn2 = fmaxf(s2w - s1w * s1w * (1.0f / Cc), 0.f);
            d = sqrtf(pn2) - 0.5f; v = (d > 0.f) ? d * d : 0.f;
            atomicAdd(&vbin[lu >> 24], v); atomicAdd(&cbin[lu >> 24], 1.f);
        }
        __syncthreads();
        if (t < Ll) {
            g_vpart[g5 * Ll + t] = vbin[t];
            g_cpart[g5 * Ll + t] = cbin[t];
        }
    } else {
        // ================= channel half-pass (32768 pts) =================
        const int id = 4 * g5 + (r5 - 1);               // 0..2047
        const int b = id >> 8;
        const int rem = id & 255;
        const int c = rem >> 1, half = rem & 1;
        float* acc = sm;             // [2 copies][64 labels][128 cols]
        float* red = sm + 16384;     // [256]

        for (int i = t; i < 16384; i += 256) acc[i] = 0.f;
        __syncthreads();

        const float4* p4 = (const float4*)(pred + (size_t)b * Cc * Nn + (size_t)c * Nn)
                           + half * 8192;
        const unsigned* lp = g_lab8 + b * (Nn / 4) + half * 8192;
        float* ap = acc + (t >> 7) * 8192 + (t & 127);  // private column

        float4 XA[4], XB[4]; unsigned LA[4], LB[4];
#pragma unroll
        for (int k = 0; k < 4; k++) { XA[k] = ldg_el(p4 + k * 256 + t); LA[k] = lp[k * 256 + t]; }

#pragma unroll 1
        for (int s = 0; s < 8; s += 2) {                // 8192 float4 total
#pragma unroll
            for (int k = 0; k < 4; k++) {
                int idx = ((s + 1) * 4 + k) * 256 + t;
                XB[k] = ldg_el(p4 + idx); LB[k] = lp[idx];
            }
#pragma unroll
            for (int k = 0; k < 4; k++) {
                ap[(LA[k] & 255) * 128]         += XA[k].x;   // bank=col%32: clean
                ap[((LA[k] >> 8) & 255) * 128]  += XA[k].y;
                ap[((LA[k] >> 16) & 255) * 128] += XA[k].z;
                ap[(LA[k] >> 24) * 128]         += XA[k].w;
            }
            if (s + 2 < 8) {
#pragma unroll
                for (int k = 0; k < 4; k++) {
                    int idx = ((s + 2) * 4 + k) * 256 + t;
                    XA[k] = ldg_el(p4 + idx); LA[k] = lp[idx];
                }
            }
#pragma unroll
            for (int k = 0; k < 4; k++) {
                ap[(LB[k] & 255) * 128]         += XB[k].x;
                ap[((LB[k] >> 8) & 255) * 128]  += XB[k].y;
                ap[((LB[k] >> 16) & 255) * 128] += XB[k].z;
                ap[(LB[k] >> 24) * 128]         += XB[k].w;
            }
        }
        __syncthreads();

        // diagonal reduce (conflict-free despite stride 128)
        const int l = t & 63, q = t >> 6;
        float s = 0.f;
#pragma unroll 8
        for (int jj = 0; jj < 32; jj++) {
            int j = (q * 32 + jj + t) & 127;
            s += acc[l * 128 + j] + acc[8192 + l * 128 + j];
        }
        red[t] = s;
        __syncthreads();
        if (t < Ll)                    // 2 adds/cell: commutative -> deterministic
            atomicAdd(&g_censum[((size_t)b * Ll + t) * Cc + c],
                      red[t] + red[t + 64] + red[t + 128] + red[t + 192]);
    }
}

// ---------------------------------------------------------------------------
// kfin: merged finalize. Grid (32, Bb); block q covers d in [q*4, q*4+4).
// Re-derives counts from L2-resident partials; q==0 adds reg + var terms.
// ---------------------------------------------------------------------------
__global__ __launch_bounds__(256) void kfin(float* __restrict__ out) {
    const int q = blockIdx.x, b = blockIdx.y, t = threadIdx.x;
    __shared__ float cen[Ll][Cc];    // 32 KB
    __shared__ float ps[256];
    __shared__ float qs[256];
    __shared__ float icnt[Ll];
    __shared__ float vc[Ll];
    __shared__ float sq[Cc];
    __shared__ float red[8];

    {   // counts + vsums: 16 slabs per thread (L2-resident, 16KB/batch)
        const int l = t & 63, sg = t >> 6;
        float cs = 0.f, vv = 0.f;
#pragma unroll 4
        for (int k = 0; k < 16; k++) {
            int idx = (b * PSLABS + sg * 16 + k) * Ll + l;
            cs += g_cpart[idx];
            vv += g_vpart[idx];
        }
        ps[t] = cs; qs[t] = vv;
    }
    __syncthreads();
    if (t < Ll) {
        float ctot = ps[t] + ps[t + 64] + ps[t + 128] + ps[t + 192];
        icnt[t] = 1.0f / ctot;
        vc[t] = (qs[t] + qs[t + 64] + qs[t + 128] + qs[t + 192]) / ctot;
    }
    __syncthreads();

    {   // normalized centers (float4: 4 consecutive c share one l)
        const float4* src = (const float4*)(g_censum + (size_t)b * Ll * Cc);
        float4* dst = (float4*)&cen[0][0];
#pragma unroll
        for (int i = 0; i < 8; i++) {
            int idx = i * 256 + t;                 // 2048 float4 cells
            float ic = icnt[idx >> 5];
            float4 v = src[idx];
            v.x *= ic; v.y *= ic; v.z *= ic; v.w *= ic;
            dst[idx] = v;
        }
    }
    __syncthreads();

    {   // sqn: half-column per thread then combine
        const int c = t & 127, h = t >> 7;
        float s = 0.f;
#pragma unroll 8
        for (int l = h * 32; l < h * 32 + 32; l++) { float v = cen[l][c]; s = fmaf(v, v, s); }
        ps[t] = s;
    }
    __syncthreads();
    if (t < Cc) sq[t] = ps[t] + ps[t + 128];
    __syncthreads();

    // gram slice: 2 accumulators per thread
    const int cc = t & 127;
    const int d0 = q * 4 + (t >> 7) * 2;
    float g0 = 0.f, g1 = 0.f;
#pragma unroll 8
    for (int l = 0; l < Ll; l++) {
        float a = cen[l][cc];
        g0 = fmaf(a, cen[l][d0 + 0], g0);
        g1 = fmaf(a, cen[l][d0 + 1], g1);
    }
    float local = 0.f;
#pragma unroll
    for (int j = 0; j < 2; j++) {
        float gg = j ? g1 : g0;
        float sqd = fmaxf(sq[cc] + sq[d0 + j] - 2.0f * gg, 0.f);
        float dist = (sqd > 0.f) ? sqrtf(sqd) : 0.f;
        float h = fmaxf(3.0f - dist, 0.f);        // 2*D_DIST
        local = fmaf(h, h, local);
    }
    local *= (1.0f / 8064.0f);                    // P_DIST / (2*L*(L-1))

    if (q == 0 && t < Cc) {
        local += 0.001f * sqrtf(sq[t]) * (1.0f / 64.0f);   // l_reg
        if (t < Ll) local += vc[t] * (1.0f / 64.0f);       // var
    }

    for (int off = 16; off > 0; off >>= 1)
        local += __shfl_down_sync(0xFFFFFFFFu, local, off);
    if ((t & 31) == 0) red[t >> 5] = local;
    __syncthreads();
    if (t == 0) {
        float s = 0.f;
#pragma unroll
        for (int w = 0; w < 8; w++) s += red[w];
        atomicAdd(out, s);
    }
}

// ---------------------------------------------------------------------------
extern "C" void kernel_launch(void* const* d_in, const int* in_sizes, int n_in,
                              void* d_out, int out_size) {
    const float* pred  = (const float*)d_in[0];
    const int*   label = (const int*)d_in[1];
    float* out = (float*)d_out;

    const int smem_bytes = (16384 + 256) * 4;     // 66560
    cudaFuncSetAttribute(kboth, cudaFuncAttributeMaxDynamicSharedMemorySize, smem_bytes);

    klab<<<128, 256>>>(label);
    kboth<<<NBLK, 256, smem_bytes>>>(pred, out, out_size);
    kfin<<<dim3(32, Bb), 256>>>(out);
}

// round 12
// speedup vs baseline: 1.6945x; 1.0261x over previous
#include <cuda_runtime.h>
#include <math.h>

#define Bb 8
#define Cc 128
#define Nn 65536
#define Ll 64
#define NPT 1024                  // point blocks (512 pts each)
#define NCHH (Bb * Cc * 2)        // 2048 channel half-blocks
#define NBLK (NPT + NCHH)         // 3072

// Scratch in device globals. g_censum zeroed by klab then atomically
// accumulated (exactly 2 adds per cell -> commutative -> deterministic).
__device__ unsigned int g_lab8[Bb * Nn / 4];     // packed uint8 labels
__device__ float g_censum[Bb * Ll * Cc];
__device__ float g_vpart[NPT * Ll];
__device__ float g_cpart[NPT * Ll];

// float4 load with L2 evict-last via cache-policy hint: pred lines are
// touched exactly twice (point pass + channel pass); retaining them turns
// the 2nd touch into an L2 hit.
__device__ __forceinline__ float4 ldg_el(const float4* p) {
    float4 v;
    unsigned long long pol;
    asm volatile("createpolicy.fractional.L2::evict_last.b64 %0, 1.0;" : "=l"(pol));
    asm volatile("ld.global.nc.L2::cache_hint.v4.f32 {%0,%1,%2,%3}, [%4], %5;"
                 : "=f"(v.x), "=f"(v.y), "=f"(v.z), "=f"(v.w)
                 : "l"(p), "l"(pol));
    return v;
}
__device__ __forceinline__ float2 ldg_el2(const float2* p) {
    float2 v;
    unsigned long long pol;
    asm volatile("createpolicy.fractional.L2::evict_last.b64 %0, 1.0;" : "=l"(pol));
    asm volatile("ld.global.nc.L2::cache_hint.v2.f32 {%0,%1}, [%2], %3;"
                 : "=f"(v.x), "=f"(v.y) : "l"(p), "l"(pol));
    return v;
}

// ---------------------------------------------------------------------------
// klab: pack labels to uint8x4, zero censum + out, and prefetch the first
// 8 MB of pred into L2 (hides under the first-kernel clock ramp).
// ---------------------------------------------------------------------------
__global__ __launch_bounds__(256) void klab(const int* __restrict__ label,
                                            const float* __restrict__ pred,
                                            float* __restrict__ out, int out_size) {
    const int t = blockIdx.x * 256 + threadIdx.x;      // 65536 threads
    const int4* l4 = (const int4*)label;
#pragma unroll
    for (int k = 0; k < 2; k++) {
        int i = t * 2 + k;
        int4 l = l4[i];
        g_lab8[i] = (unsigned)l.x | ((unsigned)l.y << 8) |
                    ((unsigned)l.z << 16) | ((unsigned)l.w << 24);
    }
    g_censum[t] = 0.0f;
    if (t < out_size) out[t] = 0.0f;
    // prefetch first 8 MB of pred (one 128B line per thread)
    asm volatile("prefetch.global.L2 [%0];" :: "l"(pred + (size_t)t * 32));
}

// ---------------------------------------------------------------------------
// kboth: merged grid, 1 point : 2 channel-half interleave (bid%3), batch-
// aligned so both passes touch the same batch within one L2 window.
// ---------------------------------------------------------------------------
__global__ __launch_bounds__(256, 3) void kboth(const float* __restrict__ pred) {
    extern __shared__ float sm[];
    const int t = threadIdx.x;
    const int bid = blockIdx.x;
    const int g3 = bid / 3, r3 = bid - 3 * g3;

    if (r3 == 0) {
        // ================= point pass (512 pts) =================
        const int b = g3 >> 7, ps = g3 & 127;
        const int n0 = ps * 512;                        // 256 thr x 2 pts
        const float2* p2 = (const float2*)(pred + (size_t)b * Cc * Nn + n0);

        float s1x = 0.f, s1y = 0.f, s2x = 0.f, s2y = 0.f;
        float2 VA[8], VB[8];
#pragma unroll
        for (int k = 0; k < 8; k++) VA[k] = ldg_el2(p2 + (size_t)k * (Nn / 2) + t);

#pragma unroll 1
        for (int cg = 0; cg < 16; cg += 2) {
#pragma unroll
            for (int k = 0; k < 8; k++)
                VB[k] = ldg_el2(p2 + (size_t)((cg + 1) * 8 + k) * (Nn / 2) + t);
#pragma unroll
            for (int k = 0; k < 8; k++) {
                s1x += VA[k].x; s2x = fmaf(VA[k].x, VA[k].x, s2x);
                s1y += VA[k].y; s2y = fmaf(VA[k].y, VA[k].y, s2y);
            }
            if (cg + 2 < 16) {
#pragma unroll
                for (int k = 0; k < 8; k++)
                    VA[k] = ldg_el2(p2 + (size_t)((cg + 2) * 8 + k) * (Nn / 2) + t);
            }
#pragma unroll
            for (int k = 0; k < 8; k++) {
                s1x += VB[k].x; s2x = fmaf(VB[k].x, VB[k].x, s2x);
                s1y += VB[k].y; s2y = fmaf(VB[k].y, VB[k].y, s2y);
            }
        }
        // labels: points n0+2t, n0+2t+1 live in word (n0/4 + t/2)
        unsigned w = g_lab8[b * (Nn / 4) + (n0 >> 2) + (t >> 1)];
        int sh = (t & 1) * 16;
        int l0 = (w >> sh) & 255, l1 = (w >> (sh + 8)) & 255;

        float* vbin = sm;            // [64]
        float* cbin = sm + 64;       // [64]
        if (t < Ll) { vbin[t] = 0.f; cbin[t] = 0.f; }
        __syncthreads();
        {
            float pn2, d, v;
            pn2 = fmaxf(s2x - s1x * s1x * (1.0f / Cc), 0.f);
            d = sqrtf(pn2) - 0.5f; v = (d > 0.f) ? d * d : 0.f;
            atomicAdd(&vbin[l0], v); atomicAdd(&cbin[l0], 1.f);
            pn2 = fmaxf(s2y - s1y * s1y * (1.0f / Cc), 0.f);
            d = sqrtf(pn2) - 0.5f; v = (d > 0.f) ? d * d : 0.f;
            atomicAdd(&vbin[l1], v); atomicAdd(&cbin[l1], 1.f);
        }
        __syncthreads();
        if (t < Ll) {
            g_vpart[g3 * Ll + t] = vbin[t];
            g_cpart[g3 * Ll + t] = cbin[t];
        }
    } else {
        // ================= channel half-pass (32768 pts) =================
        const int id = 2 * g3 + (r3 - 1);               // 0..2047
        const int b = id >> 8;
        const int rem = id & 255;
        const int c = rem >> 1, half = rem & 1;
        float* acc = sm;             // [2 copies][64 labels][128 slots]
        float* red = sm + 16384;     // [256]

        {   // float4 zeroing: 16 STS.128 per thread
            float4* az = (float4*)acc;
            float4 z = make_float4(0.f, 0.f, 0.f, 0.f);
#pragma unroll
            for (int i = 0; i < 16; i++) az[i * 256 + t] = z;
        }
        __syncthreads();

        const float4* p4 = (const float4*)(pred + (size_t)b * Cc * Nn + (size_t)c * Nn)
                           + half * 8192;
        const unsigned* lp = g_lab8 + b * (Nn / 4) + half * 8192;
        float* ap = acc + (t >> 7) * 8192 + (t & 127);  // private slot column

        float4 XA[4], XB[4]; unsigned LA[4], LB[4];
#pragma unroll
        for (int k = 0; k < 4; k++) { XA[k] = ldg_el(p4 + k * 256 + t); LA[k] = lp[k * 256 + t]; }

#pragma unroll 1
        for (int s = 0; s < 8; s += 2) {                // 8192 float4 total
#pragma unroll
            for (int k = 0; k < 4; k++) {
                int idx = ((s + 1) * 4 + k) * 256 + t;
                XB[k] = ldg_el(p4 + idx); LB[k] = lp[idx];
            }
#pragma unroll
            for (int k = 0; k < 4; k++) {
                ap[(LA[k] & 255) * 128]         += XA[k].x;   // bank=slot%32: clean
                ap[((LA[k] >> 8) & 255) * 128]  += XA[k].y;
                ap[((LA[k] >> 16) & 255) * 128] += XA[k].z;
                ap[(LA[k] >> 24) * 128]         += XA[k].w;
            }
            if (s + 2 < 8) {
#pragma unroll
                for (int k = 0; k < 4; k++) {
                    int idx = ((s + 2) * 4 + k) * 256 + t;
                    XA[k] = ldg_el(p4 + idx); LA[k] = lp[idx];
                }
            }
#pragma unroll
            for (int k = 0; k < 4; k++) {
                ap[(LB[k] & 255) * 128]         += XB[k].x;
                ap[((LB[k] >> 8) & 255) * 128]  += XB[k].y;
                ap[((LB[k] >> 16) & 255) * 128] += XB[k].z;
                ap[(LB[k] >> 24) * 128]         += XB[k].w;
            }
        }
        __syncthreads();

        // float4 diagonal reduce: row l has 32 float4 per copy; thread group
        // q (of 4) covers 8 diagonal float4 from each copy.
        {
            const int l = t & 63, q = t >> 6;
            const float4* a4 = (const float4*)acc;
            float s = 0.f;
#pragma unroll
            for (int jj = 0; jj < 8; jj++) {
                int j4 = (q * 8 + jj + l) & 31;
                float4 v0 = a4[l * 32 + j4];
                float4 v1 = a4[2048 + l * 32 + j4];
                s += (v0.x + v0.y + v0.z + v0.w) + (v1.x + v1.y + v1.z + v1.w);
            }
            red[t] = s;
        }
        __syncthreads();
        if (t < Ll)                    // 2 adds/cell: commutative -> deterministic
            atomicAdd(&g_censum[((size_t)b * Ll + t) * Cc + c],
                      red[t] + red[t + 64] + red[t + 128] + red[t + 192]);
    }
}

// ---------------------------------------------------------------------------
// kfin: merged finalize. Grid (32, Bb); block q covers d in [q*4, q*4+4).
// Re-derives counts from L2-resident partials; q==0 adds reg + var terms.
// ---------------------------------------------------------------------------
__global__ __launch_bounds__(256) void kfin(float* __restrict__ out) {
    const int q = blockIdx.x, b = blockIdx.y, t = threadIdx.x;
    __shared__ float cen[Ll][Cc];    // 32 KB
    __shared__ float ps[256];
    __shared__ float qs[256];
    __shared__ float icnt[Ll];
    __shared__ float vc[Ll];
    __shared__ float sq[Cc];
    __shared__ float red[8];

    {   // counts + vsums: 32 point-blocks per thread (128 per batch)
        const int l = t & 63, sg = t >> 6;
        float cs = 0.f, vv = 0.f;
#pragma unroll 4
        for (int k = 0; k < 32; k++) {
            int idx = (b * 128 + sg * 32 + k) * Ll + l;
            cs += g_cpart[idx];
            vv += g_vpart[idx];
        }
        ps[t] = cs; qs[t] = vv;
    }
    __syncthreads();
    if (t < Ll) {
        float ctot = ps[t] + ps[t + 64] + ps[t + 128] + ps[t + 192];
        icnt[t] = 1.0f / ctot;
        vc[t] = (qs[t] + qs[t + 64] + qs[t + 128] + qs[t + 192]) / ctot;
    }
    __syncthreads();

    {   // normalized centers (float4: 4 consecutive c share one l)
        const float4* src = (const float4*)(g_censum + (size_t)b * Ll * Cc);
        float4* dst = (float4*)&cen[0][0];
#pragma unroll
        for (int i = 0; i < 8; i++) {
            int idx = i * 256 + t;                 // 2048 float4 cells
            float ic = icnt[idx >> 5];
            float4 v = src[idx];
            v.x *= ic; v.y *= ic; v.z *= ic; v.w *= ic;
            dst[idx] = v;
        }
    }
    __syncthreads();

    {   // sqn: half-column per thread then combine
        const int c = t & 127, h = t >> 7;
        float s = 0.f;
#pragma unroll 8
        for (int l = h * 32; l < h * 32 + 32; l++) { float v = cen[l][c]; s = fmaf(v, v, s); }
        ps[t] = s;
    }
    __syncthreads();
    if (t < Cc) sq[t] = ps[t] + ps[t + 128];
    __syncthreads();

    // gram slice: 2 accumulators per thread
    const int cc = t & 127;
    const int d0 = q * 4 + (t >> 7) * 2;
    float g0 = 0.f, g1 = 0.f;
#pragma unroll 8
    for (int l = 0; l < Ll; l++) {
        float a = cen[l][cc];
        g0 = fmaf(a, cen[l][d0 + 0], g0);
        g1 = fmaf(a, cen[l][d0 + 1], g1);
    }
    float local = 0.f;
#pragma unroll
    for (int j = 0; j < 2; j++) {
        float gg = j ? g1 : g0;
        float sqd = fmaxf(sq[cc] + sq[d0 + j] - 2.0f * gg, 0.f);
        float dist = (sqd > 0.f) ? sqrtf(sqd) : 0.f;
        float h = fmaxf(3.0f - dist, 0.f);        // 2*D_DIST
        local = fmaf(h, h, local);
    }
    local *= (1.0f / 8064.0f);                    // P_DIST / (2*L*(L-1))

    if (q == 0 && t < Cc) {
        local += 0.001f * sqrtf(sq[t]) * (1.0f / 64.0f);   // l_reg
        if (t < Ll) local += vc[t] * (1.0f / 64.0f);       // var
    }

    for (int off = 16; off > 0; off >>= 1)
        local += __shfl_down_sync(0xFFFFFFFFu, local, off);
    if ((t & 31) == 0) red[t >> 5] = local;
    __syncthreads();
    if (t == 0) {
        float s = 0.f;
#pragma unroll
        for (int w = 0; w < 8; w++) s += red[w];
        atomicAdd(out, s);
    }
}

// ---------------------------------------------------------------------------
extern "C" void kernel_launch(void* const* d_in, const int* in_sizes, int n_in,
                              void* d_out, int out_size) {
    const float* pred  = (const float*)d_in[0];
    const int*   label = (const int*)d_in[1];
    float* out = (float*)d_out;

    const int smem_bytes = (16384 + 256) * 4;     // 66560
    cudaFuncSetAttribute(kboth, cudaFuncAttributeMaxDynamicSharedMemorySize, smem_bytes);

    klab<<<256, 256>>>(label, pred, out, out_size);
    kboth<<<NBLK, 256, smem_bytes>>>(pred);
    kfin<<<dim3(32, Bb), 256>>>(out);
}